// round 1
// baseline (speedup 1.0000x reference)
#include <cuda_runtime.h>

#define Bn     4096
#define Dn     256
#define NEXP   4
#define NPAIR  6
#define TM     64
#define TN     64
#define KKC    16
#define SPLITK 4
#define KSLAB  (Bn / SPLITK)     // 1024
#define NTILE  16                // (256/64)^2
#define SQ_BLOCKS 192

// -------- scratch (static device globals; no runtime allocation) ----------
__device__ float g_partMean[NEXP * 32 * Dn];          // 128 KB
__device__ float g_mean[NEXP * Dn];                   // 4 KB
__device__ float g_partC[SPLITK * NPAIR * Dn * Dn];   // 6.29 MB
__device__ float g_bsum[SQ_BLOCKS];

__constant__ int c_pi[NPAIR] = {0, 0, 0, 1, 1, 2};
__constant__ int c_pj[NPAIR] = {1, 2, 3, 2, 3, 3};

// -------- phase 1: column sums (coalesced, deterministic) -----------------
__global__ void colsum_kernel(const float* __restrict__ e0,
                              const float* __restrict__ e1,
                              const float* __restrict__ e2,
                              const float* __restrict__ e3) {
    int e  = blockIdx.y;          // expert
    int ch = blockIdx.x;          // row chunk of 128
    int t  = threadIdx.x;         // column 0..255
    const float* E = (e == 0) ? e0 : (e == 1) ? e1 : (e == 2) ? e2 : e3;
    const float* p = E + (size_t)(ch * 128) * Dn + t;
    float s = 0.0f;
#pragma unroll 8
    for (int r = 0; r < 128; r++) s += p[r * Dn];
    g_partMean[(e * 32 + ch) * Dn + t] = s;
}

__global__ void mean_kernel() {
    int e = blockIdx.x, t = threadIdx.x;
    float s = 0.0f;
#pragma unroll
    for (int c = 0; c < 32; c++) s += g_partMean[(e * 32 + c) * Dn + t];
    g_mean[e * Dn + t] = s * (1.0f / (float)Bn);
}

// -------- phase 2: centered cross-GEMM, split-K partials ------------------
// C_ij[a][b] = sum_r (Ei[r][a]-mi[a]) * (Ej[r][b]-mj[b]),  256x256 per pair.
__global__ __launch_bounds__(256, 3)
void gemm_kernel(const float* __restrict__ e0, const float* __restrict__ e1,
                 const float* __restrict__ e2, const float* __restrict__ e3) {
    int tile = blockIdx.x;                    // 0..15
    int pair = blockIdx.y;                    // 0..5
    int slab = blockIdx.z;                    // 0..SPLITK-1
    int tm = (tile >> 2) * TM;
    int tn = (tile & 3) * TN;
    int pi = c_pi[pair], pj = c_pj[pair];
    const float* A  = (pi == 0) ? e0 : (pi == 1) ? e1 : (pi == 2) ? e2 : e3;
    const float* Bm = (pj == 0) ? e0 : (pj == 1) ? e1 : (pj == 2) ? e2 : e3;

    __shared__ float As[KKC][TM];
    __shared__ float Bs[KKC][TN];
    __shared__ float mA[TM], mB[TN];

    int t = threadIdx.x;
    if (t < TM)                mA[t]      = g_mean[pi * Dn + tm + t];
    else if (t < TM + TN)      mB[t - TM] = g_mean[pj * Dn + tn + (t - TM)];
    __syncthreads();

    // loader mapping: thread t fills one float4 of As and one of Bs per K-chunk
    int lr = t >> 4;            // 0..15  (row within K-chunk)
    int lc = (t & 15) * 4;      // 0..60  (column, float4)
    float4 ma4 = *(const float4*)&mA[lc];
    float4 mb4 = *(const float4*)&mB[lc];

    // compute mapping: 4x4 micro-tile
    int tx = t & 15;            // n-group
    int ty = t >> 4;            // m-group
    float acc[4][4] = {};

    const float* Aptr = A  + tm + lc;
    const float* Bptr = Bm + tn + lc;
    int kbeg = slab * KSLAB;

    for (int k0 = kbeg; k0 < kbeg + KSLAB; k0 += KKC) {
        float4 av = *(const float4*)&Aptr[(size_t)(k0 + lr) * Dn];
        float4 bv = *(const float4*)&Bptr[(size_t)(k0 + lr) * Dn];
        av.x -= ma4.x; av.y -= ma4.y; av.z -= ma4.z; av.w -= ma4.w;
        bv.x -= mb4.x; bv.y -= mb4.y; bv.z -= mb4.z; bv.w -= mb4.w;
        *(float4*)&As[lr][lc] = av;
        *(float4*)&Bs[lr][lc] = bv;
        __syncthreads();
#pragma unroll
        for (int kk = 0; kk < KKC; kk++) {
            float4 a = *(const float4*)&As[kk][ty * 4];
            float4 b = *(const float4*)&Bs[kk][tx * 4];
            acc[0][0] += a.x * b.x; acc[0][1] += a.x * b.y; acc[0][2] += a.x * b.z; acc[0][3] += a.x * b.w;
            acc[1][0] += a.y * b.x; acc[1][1] += a.y * b.y; acc[1][2] += a.y * b.z; acc[1][3] += a.y * b.w;
            acc[2][0] += a.z * b.x; acc[2][1] += a.z * b.y; acc[2][2] += a.z * b.z; acc[2][3] += a.z * b.w;
            acc[3][0] += a.w * b.x; acc[3][1] += a.w * b.y; acc[3][2] += a.w * b.z; acc[3][3] += a.w * b.w;
        }
        __syncthreads();
    }

    // write split-K partial tile (row-contiguous float4 stores)
    float* C = g_partC + ((size_t)(slab * NPAIR + pair) * Dn + tm) * Dn + tn;
#pragma unroll
    for (int i = 0; i < 4; i++) {
        *(float4*)&C[(size_t)(ty * 4 + i) * Dn + tx * 4] =
            make_float4(acc[i][0], acc[i][1], acc[i][2], acc[i][3]);
    }
}

// -------- phase 3: combine split-K, square, block reduce ------------------
__global__ void sq_kernel() {
    const int STRIDE = NPAIR * Dn * Dn;       // per-slab stride = 393216
    int idx0 = blockIdx.x * (256 * 8) + threadIdx.x;
    float s = 0.0f;
#pragma unroll
    for (int u = 0; u < 8; u++) {
        int idx = idx0 + u * 256;
        float v = g_partC[idx] + g_partC[STRIDE + idx]
                + g_partC[2 * STRIDE + idx] + g_partC[3 * STRIDE + idx];
        s += v * v;
    }
    __shared__ float red[256];
    red[threadIdx.x] = s;
    __syncthreads();
#pragma unroll
    for (int o = 128; o > 0; o >>= 1) {
        if (threadIdx.x < o) red[threadIdx.x] += red[threadIdx.x + o];
        __syncthreads();
    }
    if (threadIdx.x == 0) g_bsum[blockIdx.x] = red[0];
}

__global__ void final_kernel(float* __restrict__ out) {
    __shared__ float red[256];
    int t = threadIdx.x;
    red[t] = (t < SQ_BLOCKS) ? g_bsum[t] : 0.0f;
    __syncthreads();
#pragma unroll
    for (int o = 128; o > 0; o >>= 1) {
        if (t < o) red[t] += red[t + o];
        __syncthreads();
    }
    if (t == 0) {
        const float denom = 4095.0f * 4095.0f;   // (B-1)^2
        float total = red[0];
        out[0] = 0.1f * (total / denom) * (1.0f / (float)NPAIR);
    }
}

// -------- launch ----------------------------------------------------------
extern "C" void kernel_launch(void* const* d_in, const int* in_sizes, int n_in,
                              void* d_out, int out_size) {
    const float* e0 = (const float*)d_in[0];
    const float* e1 = (const float*)d_in[1];
    const float* e2 = (const float*)d_in[2];
    const float* e3 = (const float*)d_in[3];
    float* out = (float*)d_out;

    colsum_kernel<<<dim3(32, NEXP), 256>>>(e0, e1, e2, e3);
    mean_kernel<<<NEXP, 256>>>();
    gemm_kernel<<<dim3(NTILE, NPAIR, SPLITK), 256>>>(e0, e1, e2, e3);
    sq_kernel<<<SQ_BLOCKS, 256>>>();
    final_kernel<<<1, 256>>>(out);
}

// round 2
// speedup vs baseline: 1.6722x; 1.6722x over previous
#include <cuda_runtime.h>
#include <cuda_bf16.h>

#define Bn     4096
#define Dn     256
#define NEXP   4
#define NPAIR  6
#define TM     64
#define TN     64
#define KC     32                 // k-chunk per smem stage
#define NKCH   (Bn / KC)          // 128 chunks
#define NTILE  16                 // (256/64)^2
#define NBLK   (NTILE * NPAIR)    // 96 gemm blocks
#define SPAD   72                 // smem row stride (bf16 elems), 144B: conflict-free ldmatrix

// -------- scratch (static device globals) ---------------------------------
__device__ float          g_partMean[NEXP * 32 * Dn];
__device__ float          g_mean[NEXP * Dn];
__device__ __nv_bfloat16  g_cz[NEXP * Bn * Dn];        // centered bf16, 8.39MB
__device__ float          g_bsum[NBLK];

__constant__ int c_pi[NPAIR] = {0, 0, 0, 1, 1, 2};
__constant__ int c_pj[NPAIR] = {1, 2, 3, 2, 3, 3};

// -------- phase 1: column sums --------------------------------------------
__global__ void colsum_kernel(const float* __restrict__ e0,
                              const float* __restrict__ e1,
                              const float* __restrict__ e2,
                              const float* __restrict__ e3) {
    int e  = blockIdx.y;
    int ch = blockIdx.x;
    int t  = threadIdx.x;
    const float* E = (e == 0) ? e0 : (e == 1) ? e1 : (e == 2) ? e2 : e3;
    const float* p = E + (size_t)(ch * 128) * Dn + t;
    float s = 0.0f;
#pragma unroll 8
    for (int r = 0; r < 128; r++) s += p[r * Dn];
    g_partMean[(e * 32 + ch) * Dn + t] = s;
}

__global__ void mean_kernel() {
    int e = blockIdx.x, t = threadIdx.x;
    float s = 0.0f;
#pragma unroll
    for (int c = 0; c < 32; c++) s += g_partMean[(e * 32 + c) * Dn + t];
    g_mean[e * Dn + t] = s * (1.0f / (float)Bn);
}

// -------- phase 2: center + convert to bf16 -------------------------------
// grid (1024, NEXP), 256 threads; one float4 per thread.
__global__ void center_kernel(const float* __restrict__ e0,
                              const float* __restrict__ e1,
                              const float* __restrict__ e2,
                              const float* __restrict__ e3) {
    int e = blockIdx.y;
    const float* E = (e == 0) ? e0 : (e == 1) ? e1 : (e == 2) ? e2 : e3;
    size_t idx4 = (size_t)blockIdx.x * 256 + threadIdx.x;   // float4 idx in expert
    float4 v = ((const float4*)E)[idx4];
    int d4 = (int)(idx4 & 63);                              // column float4 index
    float4 m = ((const float4*)(g_mean + e * Dn))[d4];
    __nv_bfloat162 lo = __floats2bfloat162_rn(v.x - m.x, v.y - m.y);
    __nv_bfloat162 hi = __floats2bfloat162_rn(v.z - m.z, v.w - m.w);
    uint2 pk;
    pk.x = *(unsigned int*)&lo;
    pk.y = *(unsigned int*)&hi;
    ((uint2*)g_cz)[(size_t)e * (Bn * Dn / 4) + idx4] = pk;
}

// -------- phase 3: bf16 tensor-core GEMM + fused squared-Frobenius --------
__device__ __forceinline__ void ldm_x4t(unsigned& r0, unsigned& r1,
                                        unsigned& r2, unsigned& r3,
                                        const void* p) {
    unsigned a = (unsigned)__cvta_generic_to_shared(p);
    asm volatile("ldmatrix.sync.aligned.m8n8.x4.trans.shared.b16 "
                 "{%0,%1,%2,%3}, [%4];"
                 : "=r"(r0), "=r"(r1), "=r"(r2), "=r"(r3) : "r"(a));
}

__device__ __forceinline__ void mma16816(float* c, unsigned a0, unsigned a1,
                                         unsigned a2, unsigned a3,
                                         unsigned b0, unsigned b1) {
    asm volatile("mma.sync.aligned.m16n8k16.row.col.f32.bf16.bf16.f32 "
                 "{%0,%1,%2,%3},{%4,%5,%6,%7},{%8,%9},{%0,%1,%2,%3};"
                 : "+f"(c[0]), "+f"(c[1]), "+f"(c[2]), "+f"(c[3])
                 : "r"(a0), "r"(a1), "r"(a2), "r"(a3), "r"(b0), "r"(b1));
}

__global__ __launch_bounds__(256, 1)
void gemm_sq_kernel() {
    __shared__ __align__(16) __nv_bfloat16 As[KC][SPAD];
    __shared__ __align__(16) __nv_bfloat16 Bs[KC][SPAD];
    __shared__ float red[8];

    int tile = blockIdx.x;                   // 0..15
    int pair = blockIdx.y;                   // 0..5
    int tm = (tile >> 2) * TM;
    int tn = (tile & 3) * TN;
    const __nv_bfloat16* A = g_cz + (size_t)c_pi[pair] * Bn * Dn;
    const __nv_bfloat16* B = g_cz + (size_t)c_pj[pair] * Bn * Dn;

    int t    = threadIdx.x;
    int lane = t & 31;
    int w    = t >> 5;                       // warp 0..7
    int wm   = (w & 3) * 16;                 // warp M offset (4 groups)
    int wn   = (w >> 2) * 32;                // warp N offset (2 groups)

    // loader mapping: warps 0-3 stage A, warps 4-7 stage B; 32B per thread
    int lt   = t & 127;
    int lk   = lt >> 2;                      // 0..31 k-row
    int lseg = (lt & 3) * 16;                // col within 64 (16 bf16 = 32B)
    const __nv_bfloat16* gsrc = (t < 128)
        ? (A + tm + lseg) : (B + tn + lseg);
    __nv_bfloat16* sdst = (t < 128) ? &As[lk][lseg] : &Bs[lk][lseg];

    // ldmatrix source addresses (fixed per thread, k0 added in loop)
    int grp = lane >> 3, r = lane & 7;
    int aRow = ((grp & 2) ? 8 : 0) + r,  aCol = wm + ((grp & 1) ? 8 : 0);
    int bRow = ((grp & 1) ? 8 : 0) + r;
    int bCol0 = wn +      ((grp & 2) ? 8 : 0);
    int bCol1 = wn + 16 + ((grp & 2) ? 8 : 0);

    float acc[4][4] = {};
    uint4 st0, st1;

    // prologue: stage chunk 0
    {
        const uint4* gp = (const uint4*)(gsrc + (size_t)lk * Dn);
        st0 = gp[0]; st1 = gp[1];
    }

    for (int c = 0; c < NKCH; ++c) {
        ((uint4*)sdst)[0] = st0;
        ((uint4*)sdst)[1] = st1;
        __syncthreads();

        if (c + 1 < NKCH) {
            const uint4* gp = (const uint4*)(gsrc + (size_t)((c + 1) * KC + lk) * Dn);
            st0 = gp[0]; st1 = gp[1];
        }

#pragma unroll
        for (int s = 0; s < 2; ++s) {
            int k0 = s * 16;
            unsigned a0, a1, a2, a3;
            ldm_x4t(a0, a1, a2, a3, &As[k0 + aRow][aCol]);
            unsigned b0, b1, b2, b3;
            ldm_x4t(b0, b1, b2, b3, &Bs[k0 + bRow][bCol0]);
            unsigned b4, b5, b6, b7;
            ldm_x4t(b4, b5, b6, b7, &Bs[k0 + bRow][bCol1]);
            mma16816(acc[0], a0, a1, a2, a3, b0, b1);
            mma16816(acc[1], a0, a1, a2, a3, b2, b3);
            mma16816(acc[2], a0, a1, a2, a3, b4, b5);
            mma16816(acc[3], a0, a1, a2, a3, b6, b7);
        }
        __syncthreads();
    }

    // fused squared-Frobenius: layout-oblivious (each C elem in exactly one reg)
    float s = 0.0f;
#pragma unroll
    for (int j = 0; j < 4; ++j)
#pragma unroll
        for (int i = 0; i < 4; ++i) s += acc[j][i] * acc[j][i];

#pragma unroll
    for (int o = 16; o > 0; o >>= 1) s += __shfl_xor_sync(0xffffffffu, s, o);
    if (lane == 0) red[w] = s;
    __syncthreads();
    if (t == 0) {
        float tot = 0.0f;
#pragma unroll
        for (int i = 0; i < 8; ++i) tot += red[i];
        g_bsum[pair * NTILE + tile] = tot;
    }
}

// -------- phase 4: final combine ------------------------------------------
__global__ void final_kernel(float* __restrict__ out) {
    __shared__ float red[128];
    int t = threadIdx.x;
    float s = (t < NBLK) ? g_bsum[t] : 0.0f;
    red[t] = s;
    __syncthreads();
#pragma unroll
    for (int o = 64; o > 0; o >>= 1) {
        if (t < o) red[t] += red[t + o];
        __syncthreads();
    }
    if (t == 0) {
        const float denom = 4095.0f * 4095.0f;
        out[0] = 0.1f * (red[0] / denom) * (1.0f / (float)NPAIR);
    }
}

// -------- launch ----------------------------------------------------------
extern "C" void kernel_launch(void* const* d_in, const int* in_sizes, int n_in,
                              void* d_out, int out_size) {
    const float* e0 = (const float*)d_in[0];
    const float* e1 = (const float*)d_in[1];
    const float* e2 = (const float*)d_in[2];
    const float* e3 = (const float*)d_in[3];
    float* out = (float*)d_out;

    colsum_kernel<<<dim3(32, NEXP), 256>>>(e0, e1, e2, e3);
    mean_kernel<<<NEXP, 256>>>();
    center_kernel<<<dim3(1024, NEXP), 256>>>(e0, e1, e2, e3);
    gemm_sq_kernel<<<dim3(NTILE, NPAIR), 256>>>();
    final_kernel<<<1, 128>>>(out);
}

// round 3
// speedup vs baseline: 2.3950x; 1.4322x over previous
#include <cuda_runtime.h>
#include <cuda_bf16.h>

#define Bn     4096
#define Dn     256
#define NEXP   4
#define NPAIR  6
#define TM     64
#define TN     64
#define KC     32
#define NKCH   (Bn / KC)          // 128 real chunks
#define NKEXT  (NKCH + 1)         // +1 tail chunk carrying the rank-1 term
#define NTILE  16
#define NBLK   (NTILE * NPAIR)    // 96
#define SPAD   72                 // 144B row stride: 16B aligned, ldmatrix conflict-free
#define STG    3                  // cp.async stages

// -------- scratch ---------------------------------------------------------
__device__ float          g_partMean[NEXP * 32 * Dn];
__device__ __nv_bfloat16  g_z[NEXP * Bn * Dn];          // raw bf16 (uncentered)
__device__ __nv_bfloat16  g_tailA[NEXP * KC * Dn];      // row0 = -sqrt(B)*mean
__device__ __nv_bfloat16  g_tailB[NEXP * KC * Dn];      // row0 = +sqrt(B)*mean
__device__ float          g_bsum[NBLK];

__constant__ int c_pi[NPAIR] = {0, 0, 0, 1, 1, 2};
__constant__ int c_pj[NPAIR] = {1, 2, 3, 2, 3, 3};

// -------- phase 1: fused fp32->bf16 convert + column partial sums ---------
// grid (32, NEXP), 256 threads. Block: 128 rows x 256 cols.
__global__ void conv_colsum_kernel(const float* __restrict__ e0,
                                   const float* __restrict__ e1,
                                   const float* __restrict__ e2,
                                   const float* __restrict__ e3) {
    int e  = blockIdx.y;
    int ch = blockIdx.x;
    const float* E = (e == 0) ? e0 : (e == 1) ? e1 : (e == 2) ? e2 : e3;
    int t  = threadIdx.x;
    int c4 = t & 63;             // float4 column index (0..63)
    int rq = t >> 6;             // row phase (0..3)

    const float4* src = (const float4*)E + (size_t)(ch * 128) * 64 + c4;
    uint2* dst = (uint2*)g_z + ((size_t)e * Bn + ch * 128) * 64 + c4;

    float4 s = make_float4(0.f, 0.f, 0.f, 0.f);
    for (int r = rq; r < 128; r += 4) {
        float4 v = src[(size_t)r * 64];
        s.x += v.x; s.y += v.y; s.z += v.z; s.w += v.w;
        __nv_bfloat162 lo = __floats2bfloat162_rn(v.x, v.y);
        __nv_bfloat162 hi = __floats2bfloat162_rn(v.z, v.w);
        uint2 pk;
        pk.x = *(unsigned*)&lo; pk.y = *(unsigned*)&hi;
        dst[(size_t)r * 64] = pk;
    }
    __shared__ float4 red[4][64];
    red[rq][c4] = s;
    __syncthreads();
    if (t < 64) {
        float4 a = red[0][t], b = red[1][t], c = red[2][t], d = red[3][t];
        float4 tot = make_float4(a.x + b.x + c.x + d.x, a.y + b.y + c.y + d.y,
                                 a.z + b.z + c.z + d.z, a.w + b.w + c.w + d.w);
        ((float4*)&g_partMean[(e * 32 + ch) * Dn])[t] = tot;
    }
}

// -------- phase 2: means -> tail chunks (+/- sqrt(B)*mean, zeros) ---------
__global__ void mean_tail_kernel() {
    int e = blockIdx.x, t = threadIdx.x;
    float s = 0.0f;
#pragma unroll
    for (int c = 0; c < 32; c++) s += g_partMean[(e * 32 + c) * Dn + t];
    float m = s * (1.0f / (float)Bn);
    float r = 64.0f * m;                       // sqrt(4096) = 64
    g_tailA[(e * KC + 0) * Dn + t] = __float2bfloat16(-r);
    g_tailB[(e * KC + 0) * Dn + t] = __float2bfloat16(r);
    __nv_bfloat16 z = __float2bfloat16(0.0f);
#pragma unroll
    for (int rr = 1; rr < KC; rr++) {
        g_tailA[(e * KC + rr) * Dn + t] = z;
        g_tailB[(e * KC + rr) * Dn + t] = z;
    }
}

// -------- phase 3: bf16 HMMA GEMM + fused squared-Frobenius ---------------
__device__ __forceinline__ void cpa16(void* smem, const void* g) {
    unsigned s = (unsigned)__cvta_generic_to_shared(smem);
    asm volatile("cp.async.cg.shared.global [%0], [%1], 16;\n" :: "r"(s), "l"(g));
}
__device__ __forceinline__ void cp_commit() {
    asm volatile("cp.async.commit_group;\n");
}
__device__ __forceinline__ void cp_wait1() {
    asm volatile("cp.async.wait_group 1;\n");
}

__device__ __forceinline__ void ldm_x4t(unsigned& r0, unsigned& r1,
                                        unsigned& r2, unsigned& r3,
                                        const void* p) {
    unsigned a = (unsigned)__cvta_generic_to_shared(p);
    asm volatile("ldmatrix.sync.aligned.m8n8.x4.trans.shared.b16 "
                 "{%0,%1,%2,%3}, [%4];"
                 : "=r"(r0), "=r"(r1), "=r"(r2), "=r"(r3) : "r"(a));
}
__device__ __forceinline__ void mma16816(float* c, unsigned a0, unsigned a1,
                                         unsigned a2, unsigned a3,
                                         unsigned b0, unsigned b1) {
    asm volatile("mma.sync.aligned.m16n8k16.row.col.f32.bf16.bf16.f32 "
                 "{%0,%1,%2,%3},{%4,%5,%6,%7},{%8,%9},{%0,%1,%2,%3};"
                 : "+f"(c[0]), "+f"(c[1]), "+f"(c[2]), "+f"(c[3])
                 : "r"(a0), "r"(a1), "r"(a2), "r"(a3), "r"(b0), "r"(b1));
}

__global__ __launch_bounds__(256, 1)
void gemm_sq_kernel() {
    __shared__ __align__(16) __nv_bfloat16 SA[STG][KC][SPAD];
    __shared__ __align__(16) __nv_bfloat16 SB[STG][KC][SPAD];
    __shared__ float red[8];

    int tile = blockIdx.x;
    int pair = blockIdx.y;
    int tm = (tile >> 2) * TM;
    int tn = (tile & 3) * TN;
    const __nv_bfloat16* A  = g_z + (size_t)c_pi[pair] * Bn * Dn + tm;
    const __nv_bfloat16* B  = g_z + (size_t)c_pj[pair] * Bn * Dn + tn;
    const __nv_bfloat16* tA = g_tailA + (size_t)c_pi[pair] * KC * Dn + tm;
    const __nv_bfloat16* tB = g_tailB + (size_t)c_pj[pair] * KC * Dn + tn;

    int t    = threadIdx.x;
    int lane = t & 31;
    int w    = t >> 5;
    int wm   = (w & 3) * 16;
    int wn   = (w >> 2) * 32;

    // loader: every thread stages one 16B of A and one of B per chunk
    int lk   = t >> 3;                       // k-row 0..31
    int lseg = (t & 7) * 8;                  // bf16 col offset (16B seg)
    size_t loff = (size_t)lk * Dn + lseg;

    int grp = lane >> 3, r = lane & 7;
    int aRow = ((grp & 2) ? 8 : 0) + r,  aCol = wm + ((grp & 1) ? 8 : 0);
    int bRow = ((grp & 1) ? 8 : 0) + r;
    int bCol0 = wn +      ((grp & 2) ? 8 : 0);
    int bCol1 = wn + 16 + ((grp & 2) ? 8 : 0);

    float acc[4][4] = {};

    // ---- pipeline ----
    auto issue = [&](int c) {
        if (c < NKEXT) {
            int st = c % STG;
            const __nv_bfloat16* sa = (c < NKCH) ? (A + (size_t)c * KC * Dn) : tA;
            const __nv_bfloat16* sb = (c < NKCH) ? (B + (size_t)c * KC * Dn) : tB;
            cpa16(&SA[st][lk][lseg], sa + loff);
            cpa16(&SB[st][lk][lseg], sb + loff);
        }
        cp_commit();
    };

    issue(0);
    issue(1);

    for (int c = 0; c < NKEXT; ++c) {
        cp_wait1();
        __syncthreads();
        issue(c + 2);

        int st = c % STG;
#pragma unroll
        for (int s = 0; s < 2; ++s) {
            int k0 = s * 16;
            unsigned a0, a1, a2, a3;
            ldm_x4t(a0, a1, a2, a3, &SA[st][k0 + aRow][aCol]);
            unsigned b0, b1, b2, b3;
            ldm_x4t(b0, b1, b2, b3, &SB[st][k0 + bRow][bCol0]);
            unsigned b4, b5, b6, b7;
            ldm_x4t(b4, b5, b6, b7, &SB[st][k0 + bRow][bCol1]);
            mma16816(acc[0], a0, a1, a2, a3, b0, b1);
            mma16816(acc[1], a0, a1, a2, a3, b2, b3);
            mma16816(acc[2], a0, a1, a2, a3, b4, b5);
            mma16816(acc[3], a0, a1, a2, a3, b6, b7);
        }
        __syncthreads();
    }

    // fused squared-Frobenius (layout-oblivious)
    float s = 0.0f;
#pragma unroll
    for (int j = 0; j < 4; ++j)
#pragma unroll
        for (int i = 0; i < 4; ++i) s += acc[j][i] * acc[j][i];
#pragma unroll
    for (int o = 16; o > 0; o >>= 1) s += __shfl_xor_sync(0xffffffffu, s, o);
    if (lane == 0) red[w] = s;
    __syncthreads();
    if (t == 0) {
        float tot = 0.0f;
#pragma unroll
        for (int i = 0; i < 8; ++i) tot += red[i];
        g_bsum[pair * NTILE + tile] = tot;
    }
}

// -------- phase 4: final combine ------------------------------------------
__global__ void final_kernel(float* __restrict__ out) {
    __shared__ float red[128];
    int t = threadIdx.x;
    red[t] = (t < NBLK) ? g_bsum[t] : 0.0f;
    __syncthreads();
#pragma unroll
    for (int o = 64; o > 0; o >>= 1) {
        if (t < o) red[t] += red[t + o];
        __syncthreads();
    }
    if (t == 0) {
        const float denom = 4095.0f * 4095.0f;
        out[0] = 0.1f * (red[0] / denom) * (1.0f / (float)NPAIR);
    }
}

// -------- launch ----------------------------------------------------------
extern "C" void kernel_launch(void* const* d_in, const int* in_sizes, int n_in,
                              void* d_out, int out_size) {
    const float* e0 = (const float*)d_in[0];
    const float* e1 = (const float*)d_in[1];
    const float* e2 = (const float*)d_in[2];
    const float* e3 = (const float*)d_in[3];
    float* out = (float*)d_out;

    conv_colsum_kernel<<<dim3(32, NEXP), 256>>>(e0, e1, e2, e3);
    mean_tail_kernel<<<NEXP, 256>>>();
    gemm_sq_kernel<<<dim3(NTILE, NPAIR), 256>>>();
    final_kernel<<<1, 128>>>(out);
}

// round 4
// speedup vs baseline: 2.8531x; 1.1913x over previous
#include <cuda_runtime.h>
#include <cuda_bf16.h>

#define Bn      4096
#define Dn      256
#define NEXP    4
#define NPAIR   6
#define TM      64
#define TN      64
#define KC      32
#define NKCH    128               // real k-chunks
#define NTILE   16
#define NBLK    (NTILE * NPAIR)   // 96
#define SPAD    72                // 144B row stride, ldmatrix conflict-free
#define STG     5                 // cp.async stages (prefetch depth 4)
#define NCHC    64                // conv chunks per expert (64 rows each)

// -------- scratch ---------------------------------------------------------
__device__ float          g_partMean[NEXP * NCHC * Dn];
__device__ __nv_bfloat16  g_z[NEXP * Bn * Dn];
__device__ float          g_bsum[NBLK];
__device__ unsigned       g_cnt;

__constant__ int c_pi[NPAIR] = {0, 0, 0, 1, 1, 2};
__constant__ int c_pj[NPAIR] = {1, 2, 3, 2, 3, 3};

// -------- kernel 1: fp32->bf16 convert + column partial sums --------------
// grid (NCHC, NEXP) = 256 blocks, 256 threads; 64 rows x 256 cols each.
__global__ void conv_colsum_kernel(const float* __restrict__ e0,
                                   const float* __restrict__ e1,
                                   const float* __restrict__ e2,
                                   const float* __restrict__ e3) {
    if (blockIdx.x == 0 && blockIdx.y == 0 && threadIdx.x == 0) g_cnt = 0;
    int e  = blockIdx.y;
    int ch = blockIdx.x;
    const float* E = (e == 0) ? e0 : (e == 1) ? e1 : (e == 2) ? e2 : e3;
    int t  = threadIdx.x;
    int c4 = t & 63;              // float4 column (0..63)
    int rq = t >> 6;              // row phase (0..3)

    const float4* src = (const float4*)E + (size_t)(ch * 64) * 64 + c4;
    uint2* dst = (uint2*)g_z + ((size_t)e * Bn + ch * 64) * 64 + c4;

    float4 s = make_float4(0.f, 0.f, 0.f, 0.f);
#pragma unroll
    for (int r = rq; r < 64; r += 4) {
        float4 v = src[(size_t)r * 64];
        s.x += v.x; s.y += v.y; s.z += v.z; s.w += v.w;
        __nv_bfloat162 lo = __floats2bfloat162_rn(v.x, v.y);
        __nv_bfloat162 hi = __floats2bfloat162_rn(v.z, v.w);
        uint2 pk;
        pk.x = *(unsigned*)&lo; pk.y = *(unsigned*)&hi;
        dst[(size_t)r * 64] = pk;
    }
    __shared__ float4 red[4][64];
    red[rq][c4] = s;
    __syncthreads();
    if (t < 64) {
        float4 a = red[0][t], b = red[1][t], c = red[2][t], d = red[3][t];
        ((float4*)&g_partMean[(e * NCHC + ch) * Dn])[t] =
            make_float4(a.x + b.x + c.x + d.x, a.y + b.y + c.y + d.y,
                        a.z + b.z + c.z + d.z, a.w + b.w + c.w + d.w);
    }
}

// -------- kernel 2: bf16 HMMA GEMM + tail + fused global reduce -----------
__device__ __forceinline__ void cpa16(void* smem, const void* g) {
    unsigned s = (unsigned)__cvta_generic_to_shared(smem);
    asm volatile("cp.async.cg.shared.global [%0], [%1], 16;\n" :: "r"(s), "l"(g));
}
__device__ __forceinline__ void cp_commit() {
    asm volatile("cp.async.commit_group;\n");
}
__device__ __forceinline__ void cp_wait3() {
    asm volatile("cp.async.wait_group 3;\n");
}
__device__ __forceinline__ void ldm_x4t(unsigned& r0, unsigned& r1,
                                        unsigned& r2, unsigned& r3,
                                        const void* p) {
    unsigned a = (unsigned)__cvta_generic_to_shared(p);
    asm volatile("ldmatrix.sync.aligned.m8n8.x4.trans.shared.b16 "
                 "{%0,%1,%2,%3}, [%4];"
                 : "=r"(r0), "=r"(r1), "=r"(r2), "=r"(r3) : "r"(a));
}
__device__ __forceinline__ void mma16816(float* c, unsigned a0, unsigned a1,
                                         unsigned a2, unsigned a3,
                                         unsigned b0, unsigned b1) {
    asm volatile("mma.sync.aligned.m16n8k16.row.col.f32.bf16.bf16.f32 "
                 "{%0,%1,%2,%3},{%4,%5,%6,%7},{%8,%9},{%0,%1,%2,%3};"
                 : "+f"(c[0]), "+f"(c[1]), "+f"(c[2]), "+f"(c[3])
                 : "r"(a0), "r"(a1), "r"(a2), "r"(a3), "r"(b0), "r"(b1));
}

__global__ __launch_bounds__(256, 1)
void gemm_sq_kernel(float* __restrict__ out) {
    __shared__ __align__(16) __nv_bfloat16 SA[STG][KC][SPAD];
    __shared__ __align__(16) __nv_bfloat16 SB[STG][KC][SPAD];
    __shared__ __nv_bfloat16 tailA[TM], tailB[TN];
    __shared__ float red[8];
    __shared__ int  s_last;
    __shared__ float fred[128];

    int tile = blockIdx.x;
    int pair = blockIdx.y;
    int tm = (tile >> 2) * TM;
    int tn = (tile & 3) * TN;
    int pi = c_pi[pair], pj = c_pj[pair];
    const __nv_bfloat16* A = g_z + (size_t)pi * Bn * Dn + tm;
    const __nv_bfloat16* B = g_z + (size_t)pj * Bn * Dn + tn;

    int t    = threadIdx.x;
    int lane = t & 31;
    int w    = t >> 5;
    int wm   = (w & 3) * 16;
    int wn   = (w >> 2) * 32;

    // loader: one 16B seg of A and one of B per chunk per thread
    int lk   = t >> 3;                        // k-row 0..31
    int lseg = (t & 7) * 8;                   // bf16 col (16B granule)
    size_t loff = (size_t)lk * Dn + lseg;

    int grp = lane >> 3, r = lane & 7;
    int aRow = ((grp & 2) ? 8 : 0) + r,  aCol = wm + ((grp & 1) ? 8 : 0);
    int bRow = ((grp & 1) ? 8 : 0) + r;
    int bCol0 = wn +      ((grp & 2) ? 8 : 0);
    int bCol1 = wn + 16 + ((grp & 2) ? 8 : 0);

    float acc[4][4] = {};

    auto issue = [&](int c) {
        if (c < NKCH) {
            int st = c % STG;
            cpa16(&SA[st][lk][lseg], A + (size_t)c * KC * Dn + loff);
            cpa16(&SB[st][lk][lseg], B + (size_t)c * KC * Dn + loff);
        }
        cp_commit();
    };

    issue(0); issue(1); issue(2); issue(3);

    // prologue (overlaps with first cp.async latency): per-tile column means
    // -> rank-1 tail row values  (A: -sqrt(B)*m, B: +sqrt(B)*m)
    if (t < TM) {
        float s = 0.0f;
#pragma unroll
        for (int c = 0; c < NCHC; c++) s += g_partMean[(pi * NCHC + c) * Dn + tm + t];
        tailA[t] = __float2bfloat16(-64.0f * (s * (1.0f / (float)Bn)));
    } else if (t < TM + TN) {
        int tt = t - TM;
        float s = 0.0f;
#pragma unroll
        for (int c = 0; c < NCHC; c++) s += g_partMean[(pj * NCHC + c) * Dn + tn + tt];
        tailB[tt] = __float2bfloat16(64.0f * (s * (1.0f / (float)Bn)));
    }

    for (int c = 0; c < NKCH; ++c) {
        cp_wait3();
        __syncthreads();
        issue(c + 4);

        int st = c % STG;
#pragma unroll
        for (int s = 0; s < 2; ++s) {
            int k0 = s * 16;
            unsigned a0, a1, a2, a3;
            ldm_x4t(a0, a1, a2, a3, &SA[st][k0 + aRow][aCol]);
            unsigned b0, b1, b2, b3;
            ldm_x4t(b0, b1, b2, b3, &SB[st][k0 + bRow][bCol0]);
            unsigned b4, b5, b6, b7;
            ldm_x4t(b4, b5, b6, b7, &SB[st][k0 + bRow][bCol1]);
            mma16816(acc[0], a0, a1, a2, a3, b0, b1);
            mma16816(acc[1], a0, a1, a2, a3, b2, b3);
            mma16816(acc[2], a0, a1, a2, a3, b4, b5);
            mma16816(acc[3], a0, a1, a2, a3, b6, b7);
        }
    }

    // ---- tail: rank-1 correction as one k=16 mma (row0 = tail, rows1-15=0)
    __syncthreads();
    {
        int trow = t >> 4;            // 0..15
        int tcol = (t & 15) * 4;      // 0..60
        __nv_bfloat16 z = __float2bfloat16(0.0f);
        __nv_bfloat16 a0 = z, a1 = z, a2 = z, a3 = z;
        __nv_bfloat16 b0 = z, b1 = z, b2 = z, b3 = z;
        if (trow == 0) {
            a0 = tailA[tcol]; a1 = tailA[tcol + 1];
            a2 = tailA[tcol + 2]; a3 = tailA[tcol + 3];
            b0 = tailB[tcol]; b1 = tailB[tcol + 1];
            b2 = tailB[tcol + 2]; b3 = tailB[tcol + 3];
        }
        SA[0][trow][tcol] = a0; SA[0][trow][tcol + 1] = a1;
        SA[0][trow][tcol + 2] = a2; SA[0][trow][tcol + 3] = a3;
        SB[0][trow][tcol] = b0; SB[0][trow][tcol + 1] = b1;
        SB[0][trow][tcol + 2] = b2; SB[0][trow][tcol + 3] = b3;
    }
    __syncthreads();
    {
        unsigned a0, a1, a2, a3;
        ldm_x4t(a0, a1, a2, a3, &SA[0][aRow][aCol]);
        unsigned b0, b1, b2, b3;
        ldm_x4t(b0, b1, b2, b3, &SB[0][bRow][bCol0]);
        unsigned b4, b5, b6, b7;
        ldm_x4t(b4, b5, b6, b7, &SB[0][bRow][bCol1]);
        mma16816(acc[0], a0, a1, a2, a3, b0, b1);
        mma16816(acc[1], a0, a1, a2, a3, b2, b3);
        mma16816(acc[2], a0, a1, a2, a3, b4, b5);
        mma16816(acc[3], a0, a1, a2, a3, b6, b7);
    }

    // ---- fused squared-Frobenius (layout-oblivious) ----
    float s = 0.0f;
#pragma unroll
    for (int j = 0; j < 4; ++j)
#pragma unroll
        for (int i = 0; i < 4; ++i) s += acc[j][i] * acc[j][i];
#pragma unroll
    for (int o = 16; o > 0; o >>= 1) s += __shfl_xor_sync(0xffffffffu, s, o);
    if (lane == 0) red[w] = s;
    __syncthreads();
    if (t == 0) {
        float tot = 0.0f;
#pragma unroll
        for (int i = 0; i < 8; ++i) tot += red[i];
        g_bsum[pair * NTILE + tile] = tot;
        __threadfence();
        unsigned tk = atomicAdd(&g_cnt, 1u);
        s_last = (tk == NBLK - 1) ? 1 : 0;
    }
    __syncthreads();

    // ---- last block: deterministic fixed-order global reduce -------------
    if (s_last) {
        __threadfence();
        if (t < 128) fred[t] = (t < NBLK) ? g_bsum[t] : 0.0f;
        __syncthreads();
#pragma unroll
        for (int o = 64; o > 0; o >>= 1) {
            if (t < o) fred[t] += fred[t + o];
            __syncthreads();
        }
        if (t == 0) {
            const float denom = 4095.0f * 4095.0f;
            out[0] = 0.1f * (fred[0] / denom) * (1.0f / (float)NPAIR);
        }
    }
}

// -------- launch ----------------------------------------------------------
extern "C" void kernel_launch(void* const* d_in, const int* in_sizes, int n_in,
                              void* d_out, int out_size) {
    const float* e0 = (const float*)d_in[0];
    const float* e1 = (const float*)d_in[1];
    const float* e2 = (const float*)d_in[2];
    const float* e3 = (const float*)d_in[3];
    float* out = (float*)d_out;

    conv_colsum_kernel<<<dim3(NCHC, NEXP), 256>>>(e0, e1, e2, e3);
    gemm_sq_kernel<<<dim3(NTILE, NPAIR), 256>>>(out);
}

// round 5
// speedup vs baseline: 3.9018x; 1.3675x over previous
#include <cuda_runtime.h>
#include <cuda_bf16.h>

#define Bn      4096
#define Dn      256
#define NEXP    4
#define NPAIR   6
#define TM      64
#define TN      64
#define KC      32
#define SPLITK  4
#define KSLAB   (Bn / SPLITK)      // 1024
#define NKL     (KSLAB / KC)       // 32 chunks per slab
#define NTILE   16
#define SPAD    72
#define STG     4                  // cp.async stages (prefetch depth 3)
#define NCHC    64
#define CSTRIDE (NPAIR * NTILE * 4096)   // 393216 floats per slab
#define SQBLK   192

// -------- scratch ---------------------------------------------------------
__device__ float          g_partMean[NEXP * NCHC * Dn];
__device__ __nv_bfloat16  g_z[NEXP * Bn * Dn];
__device__ float          g_partC[SPLITK * CSTRIDE];    // 6.29MB (L2-resident)
__device__ float          g_bsum[SQBLK];
__device__ unsigned       g_cnt;

__constant__ int c_pi[NPAIR] = {0, 0, 0, 1, 1, 2};
__constant__ int c_pj[NPAIR] = {1, 2, 3, 2, 3, 3};

// -------- kernel 1: fp32->bf16 convert + column partial sums --------------
__global__ void conv_colsum_kernel(const float* __restrict__ e0,
                                   const float* __restrict__ e1,
                                   const float* __restrict__ e2,
                                   const float* __restrict__ e3) {
    if (blockIdx.x == 0 && blockIdx.y == 0 && threadIdx.x == 0) g_cnt = 0;
    int e  = blockIdx.y;
    int ch = blockIdx.x;
    const float* E = (e == 0) ? e0 : (e == 1) ? e1 : (e == 2) ? e2 : e3;
    int t  = threadIdx.x;
    int c4 = t & 63;
    int rq = t >> 6;

    const float4* src = (const float4*)E + (size_t)(ch * 64) * 64 + c4;
    uint2* dst = (uint2*)g_z + ((size_t)e * Bn + ch * 64) * 64 + c4;

    float4 s = make_float4(0.f, 0.f, 0.f, 0.f);
#pragma unroll
    for (int r = rq; r < 64; r += 4) {
        float4 v = src[(size_t)r * 64];
        s.x += v.x; s.y += v.y; s.z += v.z; s.w += v.w;
        __nv_bfloat162 lo = __floats2bfloat162_rn(v.x, v.y);
        __nv_bfloat162 hi = __floats2bfloat162_rn(v.z, v.w);
        uint2 pk;
        pk.x = *(unsigned*)&lo; pk.y = *(unsigned*)&hi;
        dst[(size_t)r * 64] = pk;
    }
    __shared__ float4 red[4][64];
    red[rq][c4] = s;
    __syncthreads();
    if (t < 64) {
        float4 a = red[0][t], b = red[1][t], c = red[2][t], d = red[3][t];
        ((float4*)&g_partMean[(e * NCHC + ch) * Dn])[t] =
            make_float4(a.x + b.x + c.x + d.x, a.y + b.y + c.y + d.y,
                        a.z + b.z + c.z + d.z, a.w + b.w + c.w + d.w);
    }
}

// -------- kernel 2: bf16 HMMA GEMM, split-K=4, partial-C fragments --------
__device__ __forceinline__ void cpa16(void* smem, const void* g) {
    unsigned s = (unsigned)__cvta_generic_to_shared(smem);
    asm volatile("cp.async.cg.shared.global [%0], [%1], 16;\n" :: "r"(s), "l"(g));
}
__device__ __forceinline__ void cp_commit() {
    asm volatile("cp.async.commit_group;\n");
}
__device__ __forceinline__ void cp_wait2() {
    asm volatile("cp.async.wait_group 2;\n");
}
__device__ __forceinline__ void cp_wait0() {
    asm volatile("cp.async.wait_group 0;\n");
}
__device__ __forceinline__ void ldm_x4t(unsigned& r0, unsigned& r1,
                                        unsigned& r2, unsigned& r3,
                                        const void* p) {
    unsigned a = (unsigned)__cvta_generic_to_shared(p);
    asm volatile("ldmatrix.sync.aligned.m8n8.x4.trans.shared.b16 "
                 "{%0,%1,%2,%3}, [%4];"
                 : "=r"(r0), "=r"(r1), "=r"(r2), "=r"(r3) : "r"(a));
}
__device__ __forceinline__ void mma16816(float* c, unsigned a0, unsigned a1,
                                         unsigned a2, unsigned a3,
                                         unsigned b0, unsigned b1) {
    asm volatile("mma.sync.aligned.m16n8k16.row.col.f32.bf16.bf16.f32 "
                 "{%0,%1,%2,%3},{%4,%5,%6,%7},{%8,%9},{%0,%1,%2,%3};"
                 : "+f"(c[0]), "+f"(c[1]), "+f"(c[2]), "+f"(c[3])
                 : "r"(a0), "r"(a1), "r"(a2), "r"(a3), "r"(b0), "r"(b1));
}

__global__ __launch_bounds__(256, 2)
void gemm_kernel() {
    __shared__ __align__(16) __nv_bfloat16 SA[STG][KC][SPAD];
    __shared__ __align__(16) __nv_bfloat16 SB[STG][KC][SPAD];
    __shared__ __nv_bfloat16 tailA[TM], tailB[TN];

    int tile = blockIdx.x;
    int pair = blockIdx.y;
    int slab = blockIdx.z;
    int tm = (tile >> 2) * TM;
    int tn = (tile & 3) * TN;
    int pi = c_pi[pair], pj = c_pj[pair];
    const __nv_bfloat16* A = g_z + (size_t)pi * Bn * Dn + (size_t)slab * KSLAB * Dn + tm;
    const __nv_bfloat16* B = g_z + (size_t)pj * Bn * Dn + (size_t)slab * KSLAB * Dn + tn;

    int t    = threadIdx.x;
    int lane = t & 31;
    int w    = t >> 5;
    int wm   = (w & 3) * 16;
    int wn   = (w >> 2) * 32;

    int lk   = t >> 3;
    int lseg = (t & 7) * 8;
    size_t loff = (size_t)lk * Dn + lseg;

    int grp = lane >> 3, r = lane & 7;
    int aRow = ((grp & 2) ? 8 : 0) + r,  aCol = wm + ((grp & 1) ? 8 : 0);
    int bRow = ((grp & 1) ? 8 : 0) + r;
    int bCol0 = wn +      ((grp & 2) ? 8 : 0);
    int bCol1 = wn + 16 + ((grp & 2) ? 8 : 0);

    float acc[4][4] = {};

    auto issue = [&](int c) {
        if (c < NKL) {
            int st = c & 3;
            cpa16(&SA[st][lk][lseg], A + (size_t)c * KC * Dn + loff);
            cpa16(&SB[st][lk][lseg], B + (size_t)c * KC * Dn + loff);
        }
        cp_commit();
    };

    issue(0); issue(1); issue(2);

    // prologue, slab 0 only: rank-1 tail rows from column means
    if (slab == 0) {
        if (t < TM) {
            float s = 0.0f;
#pragma unroll
            for (int c = 0; c < NCHC; c++) s += g_partMean[(pi * NCHC + c) * Dn + tm + t];
            tailA[t] = __float2bfloat16(-64.0f * (s * (1.0f / (float)Bn)));
        } else if (t < TM + TN) {
            int tt = t - TM;
            float s = 0.0f;
#pragma unroll
            for (int c = 0; c < NCHC; c++) s += g_partMean[(pj * NCHC + c) * Dn + tn + tt];
            tailB[tt] = __float2bfloat16(64.0f * (s * (1.0f / (float)Bn)));
        }
    }

    for (int c = 0; c < NKL; ++c) {
        cp_wait2();
        __syncthreads();
        issue(c + 3);

        int st = c & 3;
#pragma unroll
        for (int s = 0; s < 2; ++s) {
            int k0 = s * 16;
            unsigned a0, a1, a2, a3;
            ldm_x4t(a0, a1, a2, a3, &SA[st][k0 + aRow][aCol]);
            unsigned b0, b1, b2, b3;
            ldm_x4t(b0, b1, b2, b3, &SB[st][k0 + bRow][bCol0]);
            unsigned b4, b5, b6, b7;
            ldm_x4t(b4, b5, b6, b7, &SB[st][k0 + bRow][bCol1]);
            mma16816(acc[0], a0, a1, a2, a3, b0, b1);
            mma16816(acc[1], a0, a1, a2, a3, b2, b3);
            mma16816(acc[2], a0, a1, a2, a3, b4, b5);
            mma16816(acc[3], a0, a1, a2, a3, b6, b7);
        }
    }

    // rank-1 tail as one k=16 mma (slab 0 only)
    if (slab == 0) {
        cp_wait0();
        __syncthreads();
        {
            int trow = t >> 4;
            int tcol = (t & 15) * 4;
            __nv_bfloat16 z = __float2bfloat16(0.0f);
            __nv_bfloat16 a0 = z, a1 = z, a2 = z, a3 = z;
            __nv_bfloat16 b0 = z, b1 = z, b2 = z, b3 = z;
            if (trow == 0) {
                a0 = tailA[tcol];     a1 = tailA[tcol + 1];
                a2 = tailA[tcol + 2]; a3 = tailA[tcol + 3];
                b0 = tailB[tcol];     b1 = tailB[tcol + 1];
                b2 = tailB[tcol + 2]; b3 = tailB[tcol + 3];
            }
            SA[0][trow][tcol] = a0; SA[0][trow][tcol + 1] = a1;
            SA[0][trow][tcol + 2] = a2; SA[0][trow][tcol + 3] = a3;
            SB[0][trow][tcol] = b0; SB[0][trow][tcol + 1] = b1;
            SB[0][trow][tcol + 2] = b2; SB[0][trow][tcol + 3] = b3;
        }
        __syncthreads();
        {
            unsigned a0, a1, a2, a3;
            ldm_x4t(a0, a1, a2, a3, &SA[0][aRow][aCol]);
            unsigned b0, b1, b2, b3;
            ldm_x4t(b0, b1, b2, b3, &SB[0][bRow][bCol0]);
            unsigned b4, b5, b6, b7;
            ldm_x4t(b4, b5, b6, b7, &SB[0][bRow][bCol1]);
            mma16816(acc[0], a0, a1, a2, a3, b0, b1);
            mma16816(acc[1], a0, a1, a2, a3, b2, b3);
            mma16816(acc[2], a0, a1, a2, a3, b4, b5);
            mma16816(acc[3], a0, a1, a2, a3, b6, b7);
        }
    }

    // store partial fragments, layout-oblivious, coalesced (reg r -> r*256 + t)
    float* dst = g_partC + (size_t)slab * CSTRIDE + (((size_t)pair * NTILE + tile) << 12);
#pragma unroll
    for (int j = 0; j < 4; ++j)
#pragma unroll
        for (int i = 0; i < 4; ++i)
            dst[(j * 4 + i) * 256 + t] = acc[j][i];
}

// -------- kernel 3: combine slabs, square, reduce, fused final ------------
__global__ void sq_kernel(float* __restrict__ out) {
    __shared__ float red[256];
    __shared__ int s_last;
    int t = threadIdx.x;
    int idx0 = blockIdx.x * 2048 + t;
    float s = 0.0f;
#pragma unroll
    for (int u = 0; u < 8; u++) {
        int idx = idx0 + u * 256;
        float v = g_partC[idx] + g_partC[CSTRIDE + idx]
                + g_partC[2 * CSTRIDE + idx] + g_partC[3 * CSTRIDE + idx];
        s += v * v;
    }
#pragma unroll
    for (int o = 16; o > 0; o >>= 1) s += __shfl_xor_sync(0xffffffffu, s, o);
    if ((t & 31) == 0) red[t >> 5] = s;
    __syncthreads();
    if (t == 0) {
        float tot = 0.0f;
#pragma unroll
        for (int i = 0; i < 8; ++i) tot += red[i];
        g_bsum[blockIdx.x] = tot;
        __threadfence();
        unsigned tk = atomicAdd(&g_cnt, 1u);
        s_last = (tk == SQBLK - 1) ? 1 : 0;
    }
    __syncthreads();

    if (s_last) {
        __threadfence();
        red[t] = (t < SQBLK) ? g_bsum[t] : 0.0f;
        __syncthreads();
#pragma unroll
        for (int o = 128; o > 0; o >>= 1) {
            if (t < o) red[t] += red[t + o];
            __syncthreads();
        }
        if (t == 0) {
            const float denom = 4095.0f * 4095.0f;
            out[0] = 0.1f * (red[0] / denom) * (1.0f / (float)NPAIR);
        }
    }
}

// -------- launch ----------------------------------------------------------
extern "C" void kernel_launch(void* const* d_in, const int* in_sizes, int n_in,
                              void* d_out, int out_size) {
    const float* e0 = (const float*)d_in[0];
    const float* e1 = (const float*)d_in[1];
    const float* e2 = (const float*)d_in[2];
    const float* e3 = (const float*)d_in[3];
    float* out = (float*)d_out;

    conv_colsum_kernel<<<dim3(NCHC, NEXP), 256>>>(e0, e1, e2, e3);
    gemm_kernel<<<dim3(NTILE, NPAIR, SPLITK), 256>>>();
    sq_kernel<<<SQBLK, 256>>>(out);
}